// round 1
// baseline (speedup 1.0000x reference)
#include <cuda_runtime.h>
#include <cstdint>

#define B   32
#define T   512
#define MIN 4
#define H   512
#define H2  1024
#define H3  1536
#define BT  (B*T)

#define NB  64   // blocks per direction in recurrent kernel
#define JS  8    // hidden dims per block (NB*JS == H)
#define HP  516  // padded h row stride in smem (bank-spread, 16B-aligned)

// ---------------- device scratch (static, no allocation) ----------------
__device__ float    g_embx[BT * H];        // embedded inputs (B*T, H)
__device__ float    g_gx0[(size_t)BT * H3];// x@Wx_f + b_in  (forward)
__device__ float    g_gx1[(size_t)BT * H3];// x@Wx_b + b_in  (backward)
__device__ float    g_outcat[(size_t)BT * H2]; // [out_f | out_b]
__device__ float    g_hcat[B * H2];            // [h_f | h_b]
__device__ float    g_hbuf[2][2][B * H];       // [dir][parity][b*H + j]
__device__ unsigned g_bar[2];                  // per-direction step counter

// ---------------- init: reset barrier + h0 = 0 ----------------
__global__ void init_kernel() {
    int tid = blockIdx.x * blockDim.x + threadIdx.x;
    if (tid < 2) g_bar[tid] = 0;
    for (int i = tid; i < B * H; i += gridDim.x * blockDim.x) {
        g_hbuf[0][0][i] = 0.f;
        g_hbuf[1][0][i] = 0.f;
    }
}

// ---------------- embedding gather + sum over MIN tokens ----------------
__global__ void embed_kernel(const int* __restrict__ seqs,
                             const float* __restrict__ emb) {
    int bt = blockIdx.x;                 // 0..BT-1
    int i4 = threadIdx.x * 4;            // 128 threads * 4 = 512
    const int* s = seqs + bt * MIN;
    float4 acc = make_float4(0.f, 0.f, 0.f, 0.f);
#pragma unroll
    for (int m = 0; m < MIN; m++) {
        size_t row = (size_t)s[m] * H;
        float4 v = *reinterpret_cast<const float4*>(emb + row + i4);
        acc.x += v.x; acc.y += v.y; acc.z += v.z; acc.w += v.w;
    }
    *reinterpret_cast<float4*>(g_embx + (size_t)bt * H + i4) = acc;
}

// ---------------- fp32 tiled GEMM: C[M,N] = A[M,K] @ W[K,N] + bias ----------------
// tile 128x64, BK=16, 256 threads, 8x4 micro-tile. K % 16 == 0, N % 64 == 0.
__global__ void gemm_bias_kernel(const float* __restrict__ A,
                                 const float* __restrict__ W,
                                 const float* __restrict__ bias,
                                 float* __restrict__ C,
                                 int Mr, int N, int K) {
    __shared__ float a_s[16][132];   // [k][m], padded
    __shared__ float b_s[16][64];    // [k][n]
    const int tid = threadIdx.x;
    const int m0  = blockIdx.y * 128;
    const int n0  = blockIdx.x * 64;
    const int tr  = tid >> 4;        // 0..15 -> 8 m-rows each
    const int tc  = tid & 15;        // 0..15 -> 4 n-cols each

    float acc[8][4];
#pragma unroll
    for (int i = 0; i < 8; i++)
#pragma unroll
        for (int j = 0; j < 4; j++) acc[i][j] = 0.f;

    for (int kt = 0; kt < K; kt += 16) {
        // A tile: 128x16 (2 float4 per thread), store transposed
#pragma unroll
        for (int l = 0; l < 2; l++) {
            int lin = tid + l * 256;
            int m  = lin >> 2;
            int kk = (lin & 3) * 4;
            float4 v = make_float4(0.f, 0.f, 0.f, 0.f);
            if (m0 + m < Mr)
                v = *reinterpret_cast<const float4*>(A + (size_t)(m0 + m) * K + kt + kk);
            a_s[kk + 0][m] = v.x; a_s[kk + 1][m] = v.y;
            a_s[kk + 2][m] = v.z; a_s[kk + 3][m] = v.w;
        }
        // B tile: 16x64 (1 float4 per thread)
        {
            int kk = tid >> 4;
            int n  = (tid & 15) * 4;
            float4 v = *reinterpret_cast<const float4*>(W + (size_t)(kt + kk) * N + n0 + n);
            *reinterpret_cast<float4*>(&b_s[kk][n]) = v;
        }
        __syncthreads();
#pragma unroll
        for (int kk = 0; kk < 16; kk++) {
            float a[8], bb[4];
#pragma unroll
            for (int i = 0; i < 8; i++) a[i] = a_s[kk][tr * 8 + i];
#pragma unroll
            for (int j = 0; j < 4; j++) bb[j] = b_s[kk][tc * 4 + j];
#pragma unroll
            for (int i = 0; i < 8; i++)
#pragma unroll
                for (int j = 0; j < 4; j++)
                    acc[i][j] = fmaf(a[i], bb[j], acc[i][j]);
        }
        __syncthreads();
    }
    float4 bv = *reinterpret_cast<const float4*>(bias + n0 + tc * 4);
#pragma unroll
    for (int i = 0; i < 8; i++) {
        int m = m0 + tr * 8 + i;
        if (m < Mr) {
            float4 o;
            o.x = acc[i][0] + bv.x; o.y = acc[i][1] + bv.y;
            o.z = acc[i][2] + bv.z; o.w = acc[i][3] + bv.w;
            *reinterpret_cast<float4*>(C + (size_t)m * N + n0 + tc * 4) = o;
        }
    }
}

// ---------------- persistent bidirectional GRU recurrence ----------------
// grid = 2*NB blocks (dir = blockIdx.x / NB), 256 threads.
// Each block owns JS hidden dims j0..j0+JS-1 -> 3*JS Wh columns in SMEM.
// Thread (b = tid&31, cg = tid>>5) computes gates for (batch b, dim j0+cg).
__global__ void gru_kernel(const float* __restrict__ Wh_f,
                           const float* __restrict__ brec_f,
                           const float* __restrict__ Wh_b,
                           const float* __restrict__ brec_b) {
    extern __shared__ float sm[];
    float* h_s = sm;                   // [B][HP]
    float* W_s = sm + B * HP;          // [3*JS][H]: rows 0..JS-1 = z, JS.. = r, 2JS.. = n

    const int dir = blockIdx.x / NB;
    const int jb  = blockIdx.x % NB;
    const int j0  = jb * JS;
    const int tid = threadIdx.x;
    const int b   = tid & 31;
    const int cg  = tid >> 5;          // 0..7
    const int j   = j0 + cg;

    const float* Wh   = dir ? Wh_b   : Wh_f;
    const float* brec = dir ? brec_b : brec_f;
    const float* gx   = dir ? g_gx1  : g_gx0;

    // one-time: load Wh slice into SMEM
    for (int idx = tid; idx < 3 * JS * H; idx += blockDim.x) {
        int c  = idx >> 9;             // local col 0..23
        int k  = idx & (H - 1);
        int part = c / JS;             // 0=z 1=r 2=n
        int jj   = c % JS;
        W_s[c * H + k] = Wh[(size_t)k * H3 + part * H + j0 + jj];
    }
    const float brz = brec[j];
    const float brr = brec[H + j];
    const float brn = brec[2 * H + j];
    __syncthreads();

    float* hbuf0 = g_hbuf[dir][0];
    float* hbuf1 = g_hbuf[dir][1];
    volatile unsigned* bar = &g_bar[dir];

    for (int s = 0; s < T; s++) {
        const int t = dir ? (T - 1 - s) : s;
        const float* hin  = (s & 1) ? hbuf1 : hbuf0;
        float*       hout = (s & 1) ? hbuf0 : hbuf1;

        // stage h (full B x H) into smem; bypass L1 (written by other SMs)
        for (int idx = tid * 4; idx < B * H; idx += blockDim.x * 4) {
            int bb = idx >> 9;
            int kk = idx & (H - 1);
            float4 v = __ldcg(reinterpret_cast<const float4*>(hin + idx));
            *reinterpret_cast<float4*>(&h_s[bb * HP + kk]) = v;
        }
        __syncthreads();

        // prefetch gx early to hide latency under the dot loop
        const size_t gbase = ((size_t)b * T + t) * H3;
        const float xz = gx[gbase + j];
        const float xr = gx[gbase + H + j];
        const float xn = gx[gbase + 2 * H + j];

        float az = 0.f, ar = 0.f, an = 0.f;
        const float* hr4 = &h_s[b * HP];
        const float* wz  = &W_s[cg * H];
        const float* wr  = &W_s[(JS + cg) * H];
        const float* wn  = &W_s[(2 * JS + cg) * H];
#pragma unroll 4
        for (int k = 0; k < H; k += 4) {
            float4 hv = *reinterpret_cast<const float4*>(hr4 + k);
            float4 z4 = *reinterpret_cast<const float4*>(wz + k);
            float4 r4 = *reinterpret_cast<const float4*>(wr + k);
            float4 n4 = *reinterpret_cast<const float4*>(wn + k);
            az = fmaf(hv.x, z4.x, az); az = fmaf(hv.y, z4.y, az);
            az = fmaf(hv.z, z4.z, az); az = fmaf(hv.w, z4.w, az);
            ar = fmaf(hv.x, r4.x, ar); ar = fmaf(hv.y, r4.y, ar);
            ar = fmaf(hv.z, r4.z, ar); ar = fmaf(hv.w, r4.w, ar);
            an = fmaf(hv.x, n4.x, an); an = fmaf(hv.y, n4.y, an);
            an = fmaf(hv.z, n4.z, an); an = fmaf(hv.w, n4.w, an);
        }

        const float hprev = h_s[b * HP + j];
        const float zg = 1.f / (1.f + expf(-(xz + az + brz)));
        const float rg = 1.f / (1.f + expf(-(xr + ar + brr)));
        const float hc = tanhf(xn + rg * (an + brn));
        const float hnew = zg * hprev + (1.f - zg) * hc;

        __stcg(hout + b * H + j, hnew);
        g_outcat[((size_t)b * T + t) * H2 + dir * H + j] = hnew;
        if (s == T - 1) g_hcat[b * H2 + dir * H + j] = hnew;

        // grid barrier (per direction): release writes, count, spin, acquire
        __threadfence();
        __syncthreads();
        if (tid == 0) {
            atomicAdd((unsigned*)&g_bar[dir], 1u);
            const unsigned target = (unsigned)(NB * (s + 1));
            while (*bar < target) {}
        }
        __syncthreads();
        __threadfence();
    }
}

// ---------------- launch ----------------
extern "C" void kernel_launch(void* const* d_in, const int* in_sizes, int n_in,
                              void* d_out, int out_size) {
    (void)in_sizes; (void)n_in; (void)out_size;
    const int*   seqs = (const int*)d_in[0];
    // d_in[1] = input_lengths (unused by reference)
    const float* emb  = (const float*)d_in[2];
    const float* Wx_f = (const float*)d_in[3];
    const float* Wh_f = (const float*)d_in[4];
    const float* b_f  = (const float*)d_in[5];   // (2, 3H): row0 input bias, row1 recurrent
    const float* Wx_b = (const float*)d_in[6];
    const float* Wh_b = (const float*)d_in[7];
    const float* b_b  = (const float*)d_in[8];
    const float* Wd   = (const float*)d_in[9];   // (2H, H)
    const float* bd   = (const float*)d_in[10];
    float* out = (float*)d_out;

    const int smem_gru = (B * HP + 3 * JS * H) * (int)sizeof(float); // 115200 B
    cudaFuncSetAttribute(gru_kernel, cudaFuncAttributeMaxDynamicSharedMemorySize, smem_gru);

    float *p_embx, *p_gx0, *p_gx1, *p_outcat, *p_hcat;
    cudaGetSymbolAddress((void**)&p_embx,   g_embx);
    cudaGetSymbolAddress((void**)&p_gx0,    g_gx0);
    cudaGetSymbolAddress((void**)&p_gx1,    g_gx1);
    cudaGetSymbolAddress((void**)&p_outcat, g_outcat);
    cudaGetSymbolAddress((void**)&p_hcat,   g_hcat);

    init_kernel<<<64, 256>>>();
    embed_kernel<<<BT, 128>>>(seqs, emb);

    // gx = embedded @ Wx + b_in  (both directions)
    gemm_bias_kernel<<<dim3(H3 / 64, BT / 128), 256>>>(p_embx, Wx_f, b_f, p_gx0, BT, H3, H);
    gemm_bias_kernel<<<dim3(H3 / 64, BT / 128), 256>>>(p_embx, Wx_b, b_b, p_gx1, BT, H3, H);

    // bidirectional recurrence (persistent, spin-barrier)
    gru_kernel<<<2 * NB, 256, smem_gru>>>(Wh_f, b_f + H3, Wh_b, b_b + H3);

    // outputs = [out_f|out_b] @ Wd + bd ; hidden = [h_f|h_b] @ Wd + bd
    gemm_bias_kernel<<<dim3(H / 64, BT / 128), 256>>>(p_outcat, Wd, bd, out, BT, H, H2);
    gemm_bias_kernel<<<dim3(H / 64, 1), 256>>>(p_hcat, Wd, bd, out + (size_t)BT * H, B, H, H2);
}